// round 10
// baseline (speedup 1.0000x reference)
#include <cuda_runtime.h>
#include <cuda_bf16.h>

#define BB    64
#define NN    25200
#define TOPK  1024
#define CAP   2048
#define NBINS 1024
#define CONF  0.25f
#define IOUT  0.45f
#define CHUNK 788          // ceil(25200/32)
#define RSTR  33           // row stride in words (bank-conflict-free)

// ---------------- scratch (device global: allocation-free) ----------------
__device__ float g_scores[BB * NN];

// ---------------- fused per-image NMS: one block per image ----------------
// dynamic smem (135168 B) phase-aliased:
//   A/B: shist[1024]   C/D/E: sk[2048] (u64)   F/G: rows[1024*RSTR]
__global__ __launch_bounds__(1024) void k_fused(const float* __restrict__ x,
                                                float* __restrict__ out) {
    extern __shared__ unsigned int dyn[];
    __shared__ float4       sbox[TOPK];      // 16KB  cell-ordered boxes
    __shared__ uint2        sax[TOPK];       // 8KB   (0.45*area bits, rank)
    __shared__ int          cs[257];
    __shared__ float        tops[TOPK];      // 4KB
    __shared__ int          topi[TOPK];      // 4KB
    __shared__ int          counts[256], scanbuf[256];
    __shared__ unsigned int validw[32], harw[32], keepw[32];
    __shared__ int          sT, wcnt[32], woff[32];

    int b = blockIdx.x, t = threadIdx.x;
    int w = t >> 5, lane = t & 31;

    unsigned int*       shist = dyn;
    unsigned long long* sk    = (unsigned long long*)dyn;
    unsigned int*       rows  = dyn;

    // ================= Phase A: score + smem histogram =================
    shist[t] = 0u;
    if (t == 0) sT = 0;
    if (t < 32) { harw[t] = 0u; }
    __syncthreads();
    for (int it = 0; it < 25; ++it) {
        int n = it * 1024 + t;
        if (n < NN) {
            const float* row = x + (long)(b * NN + n) * 16;
            float s = __ldg(row + 4) * __ldg(row + 15);
            g_scores[b * NN + n] = s;
            if (s > CONF) {
                int bin = min((int)((s - CONF) * (1024.0f / 0.75f)), NBINS - 1);
                atomicAdd(&shist[bin], 1u);
            }
        }
    }
    __syncthreads();

    // ================= Phase B: suffix scan -> threshold ===============
    for (int off = 1; off < NBINS; off <<= 1) {
        unsigned int v = (t + off < NBINS) ? shist[t + off] : 0u;
        __syncthreads();
        shist[t] += v;
        __syncthreads();
    }
    if (shist[t] >= TOPK) atomicMax(&sT, t);
    __syncthreads();
    int T = sT;
    sk[t] = 0ULL; sk[t + 1024] = 0ULL;   // shist dead; alias OK after sync
    __syncthreads();

    // ================= Phase C: compact (two-pass, exact offsets) ======
    int base = w * CHUNK;
    int lim = min(base + CHUNK, NN);
    {
        int cnt = 0;
        for (int it = 0; it < 25; ++it) {
            int n = base + it * 32 + lane;
            bool sel = false;
            if (n < lim) {
                float s = g_scores[b * NN + n];
                if (s > CONF) {
                    int bin = min((int)((s - CONF) * (1024.0f / 0.75f)), NBINS - 1);
                    sel = (bin >= T);
                }
            }
            cnt += __popc(__ballot_sync(0xffffffffu, sel));
        }
        if (lane == 0) wcnt[w] = cnt;
    }
    __syncthreads();
    if (t < 32) {
        int v = wcnt[t], p = v;
#pragma unroll
        for (int off = 1; off < 32; off <<= 1) {
            int y = __shfl_up_sync(0xffffffffu, p, off);
            if (t >= off) p += y;
        }
        woff[t] = p - v;
    }
    __syncthreads();
    {
        int off = woff[w];
        int run = 0;
        for (int it = 0; it < 25; ++it) {
            int n = base + it * 32 + lane;
            bool sel = false;
            float s = 0.0f;
            if (n < lim) {
                s = g_scores[b * NN + n];
                if (s > CONF) {
                    int bin = min((int)((s - CONF) * (1024.0f / 0.75f)), NBINS - 1);
                    sel = (bin >= T);
                }
            }
            unsigned int m = __ballot_sync(0xffffffffu, sel);
            if (sel) {
                int pos = off + run + __popc(m & ((1u << lane) - 1u));
                if (pos < CAP) {
                    sk[pos] = ((unsigned long long)__float_as_uint(s) << 32) |
                              (unsigned long long)(0xFFFFFFFFu - (unsigned)n);
                }
            }
            run += __popc(m);
        }
    }
    __syncthreads();

    // ================= Phase D: bitonic sort desc (2048) ===============
    for (int k = 2; k <= CAP; k <<= 1) {
        for (int j = k >> 1; j > 0; j >>= 1) {
            for (int e = t; e < CAP; e += 1024) {
                int ixj = e ^ j;
                if (ixj > e) {
                    unsigned long long a = sk[e], c = sk[ixj];
                    bool desc = ((e & k) == 0);
                    if (desc ? (a < c) : (a > c)) { sk[e] = c; sk[ixj] = a; }
                }
            }
            __syncthreads();
        }
    }

    // ================= Phase E: extract + spatial bin ==================
    unsigned long long key = sk[t];
    float sc = __uint_as_float((unsigned)(key >> 32));
    int idx = (key == 0ULL) ? 0 : (int)(0xFFFFFFFFu - (unsigned)(key & 0xFFFFFFFFu));
    if (idx < 0 || idx >= NN) idx = 0;
    sc = (key == 0ULL) ? 0.0f : sc;
    tops[t] = sc;
    topi[t] = idx;
    unsigned int vb = __ballot_sync(0xffffffffu, sc > 0.0f);
    if (lane == 0) validw[w] = vb;

    const float4* rowq = (const float4*)(x + (long)(b * NN + idx) * 16);
    float4 c0 = rowq[0];
    float hw = c0.z * 0.5f, hh = c0.w * 0.5f;
    float4 box = make_float4(c0.x - hw, c0.y - hh, c0.x + hw, c0.y + hh);
    float sv = 0.45f * (fmaxf(box.z - box.x, 0.0f) * fmaxf(box.w - box.y, 0.0f));
    int cellx = min(15, max(0, (int)(c0.x * 0.025f)));
    int celly = min(15, max(0, (int)(c0.y * 0.025f)));
    int cell = celly * 16 + cellx;

    if (t < 256) counts[t] = 0;
    __syncthreads();
    atomicAdd(&counts[cell], 1);
    __syncthreads();
    if (t < 256) scanbuf[t] = counts[t];
    __syncthreads();
    for (int off = 1; off < 256; off <<= 1) {
        int add = 0;
        if (t < 256 && t >= off) add = scanbuf[t - off];
        __syncthreads();
        if (t < 256) scanbuf[t] += add;
        __syncthreads();
    }
    if (t == 0) cs[0] = 0;
    if (t < 256) { cs[t + 1] = scanbuf[t]; counts[t] = (t == 0) ? 0 : scanbuf[t - 1]; }
    __syncthreads();
    {
        int pos = atomicAdd(&counts[cell], 1);
        sbox[pos] = box;
        sax[pos] = make_uint2(__float_as_uint(sv), (unsigned)t);
    }
    __syncthreads();   // sk dead; rows may alias now

    // ================= Phase F: pairs (rank-indexed rows, no atomics) ==
    for (int i = t; i < TOPK * RSTR; i += 1024) rows[i] = 0u;
    __syncthreads();

    {
        float4 bs = sbox[t];
        uint2 axs = sax[t];
        float u = __uint_as_float(axs.x);
        int rs = (int)axs.y;
        unsigned int* rowp = &rows[rs * RSTR];   // exclusively owned by this thread
        bool any = false;

        int cl = max(0, (int)((bs.x - 64.5f) * 0.025f));
        int cr = min(15, (int)((bs.z + 64.5f) * 0.025f));
        int ct = max(0, (int)((bs.y - 64.5f) * 0.025f));
        int cb = min(15, (int)((bs.w + 64.5f) * 0.025f));

        for (int cy = ct; cy <= cb; ++cy) {
            int e0 = cs[cy * 16 + cl];
            int e1 = cs[cy * 16 + cr + 1];
#pragma unroll 2
            for (int e = e0; e < e1; ++e) {
                float4 be = sbox[e];
                uint2 axe = sax[e];
                float ix1 = fmaxf(bs.x, be.x), iy1 = fmaxf(bs.y, be.y);
                float ix2 = fminf(bs.z, be.z), iy2 = fminf(bs.w, be.w);
                float inter = fmaxf(ix2 - ix1, 0.0f) * fmaxf(iy2 - iy1, 0.0f);
                float sden = u + __uint_as_float(axe.x);
                float diff = fmaf(1.45f, inter, -sden);
                bool bit;
                if (fabsf(diff) <= 2e-5f * sden) {   // rare: exact IEEE path
                    float ai = fmaxf(bs.z - bs.x, 0.0f) * fmaxf(bs.w - bs.y, 0.0f);
                    float aj = fmaxf(be.z - be.x, 0.0f) * fmaxf(be.w - be.y, 0.0f);
                    float den = (ai + aj - inter) + 1e-9f;
                    bit = (__fdiv_rn(inter, den) > IOUT);
                } else {
                    bit = (diff > 0.0f);
                }
                int re = (int)axe.y;
                if (bit && re > rs) { rowp[re >> 5] |= 1u << (re & 31); any = true; }
            }
        }
        if (any) atomicOr(&harw[rs >> 5], 1u << (rs & 31));
    }
    __syncthreads();

    // ================= Phase G: serial greedy scan (warp 0) ============
    if (t < 32) {
        unsigned int removed = 0u;
        unsigned int vwl = validw[lane];
        for (int wi = 0; wi < 32; ++wi) {
            unsigned int alive = __shfl_sync(0xffffffffu, vwl & ~removed, wi);
            unsigned int evt = alive & harw[wi];               // uniform LDS
            while (evt) {
                int j = __ffs(evt) - 1;                        // warp-uniform
                evt &= evt - 1u;
                int rbase = ((wi << 5) + j) * RSTR;
                unsigned int rw = rows[rbase + lane];          // per-lane LDS
                unsigned int au = rows[rbase + wi];            // uniform LDS broadcast
                removed |= rw;
                alive &= ~au;
                evt &= alive;
            }
            if (lane == 0) keepw[wi] = alive;
        }
    }
    __syncthreads();

    // ================= Phase H: output =================================
    unsigned int kept = (keepw[t >> 5] >> (t & 31)) & 1u;
    float4* orow = (float4*)(out + (long)(b * TOPK + t) * 16);
    if (kept) {
        int oidx = topi[t];
        const float4* row = (const float4*)(x + (long)(b * NN + oidx) * 16);
        float4 d0 = row[0], d1 = row[1], d2 = row[2], d3 = row[3];
        float hw2 = d0.z * 0.5f, hh2 = d0.w * 0.5f;
        orow[0] = make_float4(d0.x - hw2, d0.y - hh2, d0.x + hw2, d0.y + hh2);
        orow[1] = make_float4(tops[t], d1.y, d1.z, d1.w);
        orow[2] = d2;
        orow[3] = make_float4(d3.x, d3.y, d3.z, 0.0f);
    } else {
        float4 z = make_float4(0.0f, 0.0f, 0.0f, 0.0f);
        orow[0] = z; orow[1] = z; orow[2] = z; orow[3] = z;
    }
}

// ---------------- launch ----------------
extern "C" void kernel_launch(void* const* d_in, const int* in_sizes, int n_in,
                              void* d_out, int out_size) {
    const float* x = (const float*)d_in[0];
    float* out = (float*)d_out;
    (void)in_sizes; (void)n_in; (void)out_size;

    const int dyn_smem = TOPK * RSTR * 4;   // 135168 bytes
    cudaFuncSetAttribute(k_fused, cudaFuncAttributeMaxDynamicSharedMemorySize, dyn_smem);
    k_fused<<<BB, 1024, dyn_smem>>>(x, out);
}

// round 11
// speedup vs baseline: 1.0266x; 1.0266x over previous
#include <cuda_runtime.h>
#include <cuda_bf16.h>

#define BB    64
#define NN    25200
#define TOPK  1024
#define CAP   2048
#define NBINS 1024
#define CONF  0.25f
#define IOUT  0.45f
#define CHUNK 788          // ceil(25200/32)
#define RSTR  33           // row stride in words (bank-conflict-free)

// ---------------- scratch (device globals: allocation-free) ----------------
__device__ float        g_scores[BB * NN];
__device__ unsigned int g_hist[BB * NBINS];

// ---------------- K1: WIDE score + histogram (full-chip HBM read) ----------
__global__ __launch_bounds__(256) void k_score(const float* __restrict__ x) {
    int b = blockIdx.y;
#pragma unroll
    for (int a = 0; a < 4; ++a) {
        int n = blockIdx.x * 1024 + a * 256 + threadIdx.x;
        if (n < NN) {
            const float* row = x + (long)(b * NN + n) * 16;
            float obj = __ldg(row + 4);
            float cls = __ldg(row + 15);
            float s = obj * cls;
            g_scores[b * NN + n] = s;
            if (s > CONF) {
                int bin = min((int)((s - CONF) * (1024.0f / 0.75f)), NBINS - 1);
                atomicAdd(&g_hist[b * NBINS + bin], 1u);
            }
        }
    }
}

// ---------------- K2: fused rest — one block per image --------------------
// dynamic smem (135168 B) phase-aliased:
//   B: shist[1024]   C/D/E: sk[2048] (u64)   F/G: rows[1024*RSTR]
__global__ __launch_bounds__(1024) void k_rest(const float* __restrict__ x,
                                               float* __restrict__ out) {
    extern __shared__ unsigned int dyn[];
    __shared__ float4       sbox[TOPK];      // 16KB  cell-ordered boxes
    __shared__ uint2        sax[TOPK];       // 8KB   (0.45*area bits, rank)
    __shared__ int          cs[257];
    __shared__ float        tops[TOPK];      // 4KB
    __shared__ int          topi[TOPK];      // 4KB
    __shared__ int          counts[256], scanbuf[256];
    __shared__ unsigned int validw[32], harw[32], keepw[32];
    __shared__ int          sT, wcnt[32], woff[32];

    int b = blockIdx.x, t = threadIdx.x;
    int w = t >> 5, lane = t & 31;

    unsigned int*       shist = dyn;
    unsigned long long* sk    = (unsigned long long*)dyn;
    unsigned int*       rows  = dyn;

    // ================= Phase B: threshold (suffix scan), self-reset hist ==
    shist[t] = g_hist[b * NBINS + t];
    g_hist[b * NBINS + t] = 0u;          // replay-safe reset
    if (t == 0) sT = 0;
    if (t < 32) harw[t] = 0u;
    __syncthreads();
    for (int off = 1; off < NBINS; off <<= 1) {
        unsigned int v = (t + off < NBINS) ? shist[t + off] : 0u;
        __syncthreads();
        shist[t] += v;
        __syncthreads();
    }
    if (shist[t] >= TOPK) atomicMax(&sT, t);
    __syncthreads();
    int T = sT;
    sk[t] = 0ULL; sk[t + 1024] = 0ULL;   // shist dead; alias OK after sync
    __syncthreads();

    // ================= Phase C: compact (two-pass, exact offsets) =========
    int base = w * CHUNK;
    int lim = min(base + CHUNK, NN);
    {
        int cnt = 0;
        for (int it = 0; it < 25; ++it) {
            int n = base + it * 32 + lane;
            bool sel = false;
            if (n < lim) {
                float s = g_scores[b * NN + n];
                if (s > CONF) {
                    int bin = min((int)((s - CONF) * (1024.0f / 0.75f)), NBINS - 1);
                    sel = (bin >= T);
                }
            }
            cnt += __popc(__ballot_sync(0xffffffffu, sel));
        }
        if (lane == 0) wcnt[w] = cnt;
    }
    __syncthreads();
    if (t < 32) {
        int v = wcnt[t], p = v;
#pragma unroll
        for (int off = 1; off < 32; off <<= 1) {
            int y = __shfl_up_sync(0xffffffffu, p, off);
            if (t >= off) p += y;
        }
        woff[t] = p - v;
    }
    __syncthreads();
    {
        int off = woff[w];
        int run = 0;
        for (int it = 0; it < 25; ++it) {
            int n = base + it * 32 + lane;
            bool sel = false;
            float s = 0.0f;
            if (n < lim) {
                s = g_scores[b * NN + n];
                if (s > CONF) {
                    int bin = min((int)((s - CONF) * (1024.0f / 0.75f)), NBINS - 1);
                    sel = (bin >= T);
                }
            }
            unsigned int m = __ballot_sync(0xffffffffu, sel);
            if (sel) {
                int pos = off + run + __popc(m & ((1u << lane) - 1u));
                if (pos < CAP) {
                    sk[pos] = ((unsigned long long)__float_as_uint(s) << 32) |
                              (unsigned long long)(0xFFFFFFFFu - (unsigned)n);
                }
            }
            run += __popc(m);
        }
    }
    __syncthreads();

    // ================= Phase D: bitonic sort desc (2048) ==================
    for (int k = 2; k <= CAP; k <<= 1) {
        for (int j = k >> 1; j > 0; j >>= 1) {
            for (int e = t; e < CAP; e += 1024) {
                int ixj = e ^ j;
                if (ixj > e) {
                    unsigned long long a = sk[e], c = sk[ixj];
                    bool desc = ((e & k) == 0);
                    if (desc ? (a < c) : (a > c)) { sk[e] = c; sk[ixj] = a; }
                }
            }
            __syncthreads();
        }
    }

    // ================= Phase E: extract + spatial bin ======================
    unsigned long long key = sk[t];
    float sc = __uint_as_float((unsigned)(key >> 32));
    int idx = (key == 0ULL) ? 0 : (int)(0xFFFFFFFFu - (unsigned)(key & 0xFFFFFFFFu));
    if (idx < 0 || idx >= NN) idx = 0;
    sc = (key == 0ULL) ? 0.0f : sc;
    tops[t] = sc;
    topi[t] = idx;
    unsigned int vb = __ballot_sync(0xffffffffu, sc > 0.0f);
    if (lane == 0) validw[w] = vb;

    const float4* rowq = (const float4*)(x + (long)(b * NN + idx) * 16);
    float4 c0 = rowq[0];
    float hw = c0.z * 0.5f, hh = c0.w * 0.5f;
    float4 box = make_float4(c0.x - hw, c0.y - hh, c0.x + hw, c0.y + hh);
    float sv = 0.45f * (fmaxf(box.z - box.x, 0.0f) * fmaxf(box.w - box.y, 0.0f));
    int cellx = min(15, max(0, (int)(c0.x * 0.025f)));
    int celly = min(15, max(0, (int)(c0.y * 0.025f)));
    int cell = celly * 16 + cellx;

    if (t < 256) counts[t] = 0;
    __syncthreads();
    atomicAdd(&counts[cell], 1);
    __syncthreads();
    if (t < 256) scanbuf[t] = counts[t];
    __syncthreads();
    for (int off = 1; off < 256; off <<= 1) {
        int add = 0;
        if (t < 256 && t >= off) add = scanbuf[t - off];
        __syncthreads();
        if (t < 256) scanbuf[t] += add;
        __syncthreads();
    }
    if (t == 0) cs[0] = 0;
    if (t < 256) { cs[t + 1] = scanbuf[t]; counts[t] = (t == 0) ? 0 : scanbuf[t - 1]; }
    __syncthreads();
    {
        int pos = atomicAdd(&counts[cell], 1);
        sbox[pos] = box;
        sax[pos] = make_uint2(__float_as_uint(sv), (unsigned)t);
    }
    __syncthreads();   // sk dead; rows may alias now

    // ================= Phase F: pairs (rank-indexed rows, no atomics) =====
    for (int i = t; i < TOPK * RSTR; i += 1024) rows[i] = 0u;
    __syncthreads();

    {
        float4 bs = sbox[t];
        uint2 axs = sax[t];
        float u = __uint_as_float(axs.x);
        int rs = (int)axs.y;
        unsigned int* rowp = &rows[rs * RSTR];   // exclusively owned
        bool any = false;

        int cl = max(0, (int)((bs.x - 64.5f) * 0.025f));
        int cr = min(15, (int)((bs.z + 64.5f) * 0.025f));
        int ct = max(0, (int)((bs.y - 64.5f) * 0.025f));
        int cb = min(15, (int)((bs.w + 64.5f) * 0.025f));

        for (int cy = ct; cy <= cb; ++cy) {
            int e0 = cs[cy * 16 + cl];
            int e1 = cs[cy * 16 + cr + 1];
#pragma unroll 2
            for (int e = e0; e < e1; ++e) {
                float4 be = sbox[e];
                uint2 axe = sax[e];
                float ix1 = fmaxf(bs.x, be.x), iy1 = fmaxf(bs.y, be.y);
                float ix2 = fminf(bs.z, be.z), iy2 = fminf(bs.w, be.w);
                float inter = fmaxf(ix2 - ix1, 0.0f) * fmaxf(iy2 - iy1, 0.0f);
                float sden = u + __uint_as_float(axe.x);
                float diff = fmaf(1.45f, inter, -sden);
                bool bit;
                if (fabsf(diff) <= 2e-5f * sden) {   // rare: exact IEEE path
                    float ai = fmaxf(bs.z - bs.x, 0.0f) * fmaxf(bs.w - bs.y, 0.0f);
                    float aj = fmaxf(be.z - be.x, 0.0f) * fmaxf(be.w - be.y, 0.0f);
                    float den = (ai + aj - inter) + 1e-9f;
                    bit = (__fdiv_rn(inter, den) > IOUT);
                } else {
                    bit = (diff > 0.0f);
                }
                int re = (int)axe.y;
                if (bit && re > rs) { rowp[re >> 5] |= 1u << (re & 31); any = true; }
            }
        }
        if (any) atomicOr(&harw[rs >> 5], 1u << (rs & 31));
    }
    __syncthreads();

    // ================= Phase G: serial greedy scan (warp 0) ===============
    if (t < 32) {
        unsigned int removed = 0u;
        unsigned int vwl = validw[lane];
        for (int wi = 0; wi < 32; ++wi) {
            unsigned int alive = __shfl_sync(0xffffffffu, vwl & ~removed, wi);
            unsigned int evt = alive & harw[wi];               // uniform LDS
            while (evt) {
                int j = __ffs(evt) - 1;                        // warp-uniform
                evt &= evt - 1u;
                int rbase = ((wi << 5) + j) * RSTR;
                unsigned int rw = rows[rbase + lane];          // per-lane LDS
                unsigned int au = rows[rbase + wi];            // uniform LDS broadcast
                removed |= rw;
                alive &= ~au;
                evt &= alive;
            }
            if (lane == 0) keepw[wi] = alive;
        }
    }
    __syncthreads();

    // ================= Phase H: output =====================================
    unsigned int kept = (keepw[t >> 5] >> (t & 31)) & 1u;
    float4* orow = (float4*)(out + (long)(b * TOPK + t) * 16);
    if (kept) {
        int oidx = topi[t];
        const float4* row = (const float4*)(x + (long)(b * NN + oidx) * 16);
        float4 d0 = row[0], d1 = row[1], d2 = row[2], d3 = row[3];
        float hw2 = d0.z * 0.5f, hh2 = d0.w * 0.5f;
        orow[0] = make_float4(d0.x - hw2, d0.y - hh2, d0.x + hw2, d0.y + hh2);
        orow[1] = make_float4(tops[t], d1.y, d1.z, d1.w);
        orow[2] = d2;
        orow[3] = make_float4(d3.x, d3.y, d3.z, 0.0f);
    } else {
        float4 z = make_float4(0.0f, 0.0f, 0.0f, 0.0f);
        orow[0] = z; orow[1] = z; orow[2] = z; orow[3] = z;
    }
}

// ---------------- launch ----------------
extern "C" void kernel_launch(void* const* d_in, const int* in_sizes, int n_in,
                              void* d_out, int out_size) {
    const float* x = (const float*)d_in[0];
    float* out = (float*)d_out;
    (void)in_sizes; (void)n_in; (void)out_size;

    const int dyn_smem = TOPK * RSTR * 4;   // 135168 bytes
    cudaFuncSetAttribute(k_rest, cudaFuncAttributeMaxDynamicSharedMemorySize, dyn_smem);

    {
        dim3 g((NN + 1023) / 1024, BB);
        k_score<<<g, 256>>>(x);
    }
    k_rest<<<BB, 1024, dyn_smem>>>(x, out);
}